// round 1
// baseline (speedup 1.0000x reference)
#include <cuda_runtime.h>
#include <cuda_bf16.h>

// Problem constants
#define NB 2
#define NS 2048
#define NH 32
#define NHKV 8
#define ND 64
#define NHID 2048
#define NG 4
#define ATT_SCALE 0.125f   // 1/sqrt(64)

// Scratch (no cudaMalloc allowed): q,k,v post-projection (+RoPE in place), attn output
__device__ float g_q[(size_t)NB * NS * NH * ND];      // [b,s,h,d]   33.5 MB
__device__ float g_k[(size_t)NB * NS * NHKV * ND];    // [b,s,hk,d]   8.4 MB
__device__ float g_v[(size_t)NB * NS * NHKV * ND];    // [b,s,hk,d]   8.4 MB
__device__ float g_attn[(size_t)NB * NS * NH * ND];   // [b,s,h,d]   33.5 MB

// ---------------------------------------------------------------------------
// Generic fp32 GEMM: C[M,N] = A[M,K] @ W[K,N], M=4096, K=2048 fixed.
// 128x128 block, BK=16, 256 threads, 8x8 register micro-tile.
// ---------------------------------------------------------------------------
__global__ __launch_bounds__(256) void gemm128(const float* __restrict__ A,
                                               const float* __restrict__ W,
                                               float* __restrict__ C, int N) {
    const int K = NHID;
    __shared__ float As[16][132];   // A tile transposed [k][m], padded
    __shared__ float Bs[16][128];   // W tile [k][n]

    int tid = threadIdx.x;
    int ty = tid >> 4;          // 0..15
    int tx = tid & 15;          // 0..15
    int ar = tid >> 2;          // 0..63  (A load row)
    int ac = (tid & 3) << 2;    // 0,4,8,12 (A load col group)
    int br = tid >> 4;          // 0..15  (W load row)
    int bc = (tid & 15) << 3;   // 0..120 (W load col group)

    const float* Ab = A + (size_t)blockIdx.y * 128 * K;
    const float* Wb = W + (size_t)blockIdx.x * 128;

    float acc[8][8];
#pragma unroll
    for (int i = 0; i < 8; i++)
#pragma unroll
        for (int j = 0; j < 8; j++) acc[i][j] = 0.f;

    for (int k0 = 0; k0 < K; k0 += 16) {
        float4 a0 = *(const float4*)(Ab + (size_t)ar * K + k0 + ac);
        float4 a1 = *(const float4*)(Ab + (size_t)(ar + 64) * K + k0 + ac);
        float4 b0 = *(const float4*)(Wb + (size_t)(k0 + br) * N + bc);
        float4 b1 = *(const float4*)(Wb + (size_t)(k0 + br) * N + bc + 4);
        __syncthreads();
        As[ac    ][ar]      = a0.x; As[ac + 1][ar]      = a0.y;
        As[ac + 2][ar]      = a0.z; As[ac + 3][ar]      = a0.w;
        As[ac    ][ar + 64] = a1.x; As[ac + 1][ar + 64] = a1.y;
        As[ac + 2][ar + 64] = a1.z; As[ac + 3][ar + 64] = a1.w;
        *(float4*)&Bs[br][bc]     = b0;
        *(float4*)&Bs[br][bc + 4] = b1;
        __syncthreads();
#pragma unroll
        for (int kk = 0; kk < 16; kk++) {
            float a[8], b[8];
            *(float4*)(a)     = *(const float4*)&As[kk][ty * 8];
            *(float4*)(a + 4) = *(const float4*)&As[kk][ty * 8 + 4];
            *(float4*)(b)     = *(const float4*)&Bs[kk][tx * 8];
            *(float4*)(b + 4) = *(const float4*)&Bs[kk][tx * 8 + 4];
#pragma unroll
            for (int i = 0; i < 8; i++)
#pragma unroll
                for (int j = 0; j < 8; j++)
                    acc[i][j] = fmaf(a[i], b[j], acc[i][j]);
        }
    }

    int crow = blockIdx.y * 128 + ty * 8;
    int ccol = blockIdx.x * 128 + tx * 8;
#pragma unroll
    for (int i = 0; i < 8; i++) {
        float4 o0 = make_float4(acc[i][0], acc[i][1], acc[i][2], acc[i][3]);
        float4 o1 = make_float4(acc[i][4], acc[i][5], acc[i][6], acc[i][7]);
        *(float4*)(C + (size_t)(crow + i) * N + ccol)     = o0;
        *(float4*)(C + (size_t)(crow + i) * N + ccol + 4) = o1;
    }
}

// ---------------------------------------------------------------------------
// RoPE in-place on g_q and g_k. One thread owns a (d, d+32) pair -> no race.
// position_ids is arange(S) in this problem; row index s used directly.
// ---------------------------------------------------------------------------
__global__ void rope_kernel(const float* __restrict__ cosb,
                            const float* __restrict__ sinb) {
    int bs = blockIdx.x;                    // 0..NB*NS-1
    int s = bs & (NS - 1);
    const float* cp = cosb + (size_t)s * ND;
    const float* sp = sinb + (size_t)s * ND;
    // (NH + NHKV) heads * 32 pairs = 1280 tasks
    for (int t = threadIdx.x; t < (NH + NHKV) * 32; t += blockDim.x) {
        int head = t >> 5;
        int d = t & 31;
        float* base;
        if (head < NH)
            base = g_q + (((size_t)bs * NH + head) * ND);
        else
            base = g_k + (((size_t)bs * NHKV + (head - NH)) * ND);
        float x1 = base[d];
        float x2 = base[d + 32];
        float c1 = cp[d], s1 = sp[d];
        float c2 = cp[d + 32], s2 = sp[d + 32];
        base[d]      = x1 * c1 - x2 * s1;   // rot_half lower: -x2
        base[d + 32] = x2 * c2 + x1 * s2;   // rot_half upper: +x1
    }
}

// ---------------------------------------------------------------------------
// Flash attention, fp32. grid = (S/64, H, B), 256 threads.
// BM=BN=64, 4x4 micro-tile per thread. K stored transposed in the shared
// K/V buffer (conflict-free without padding); V reuses the same buffer.
// ---------------------------------------------------------------------------
__global__ __launch_bounds__(256) void flash64(const float* __restrict__ mask) {
    __shared__ float Qs[64][64];    // [row][d], pre-scaled by ATT_SCALE
    __shared__ float KVs[64][64];   // K phase: [d][sk] ; V phase: [sk][d]
    __shared__ float Ps[64][64];    // probs [row][sk]

    int tid = threadIdx.x;
    int ty = tid >> 4;      // 0..15 -> rows 4ty..4ty+3
    int tx = tid & 15;      // 0..15 -> cols 4tx..4tx+3
    int sq0 = blockIdx.x * 64;
    int h = blockIdx.y;
    int b = blockIdx.z;
    int kvh = h >> 2;       // G=4

    for (int idx = tid; idx < 1024; idx += 256) {
        int r = idx >> 4, c = (idx & 15) << 2;
        float4 v = *(const float4*)(g_q +
            ((((size_t)b * NS + sq0 + r) * NH + h) * ND + c));
        Qs[r][c]     = v.x * ATT_SCALE;
        Qs[r][c + 1] = v.y * ATT_SCALE;
        Qs[r][c + 2] = v.z * ATT_SCALE;
        Qs[r][c + 3] = v.w * ATT_SCALE;
    }

    float m_i[4], l_i[4], acc[4][4];
#pragma unroll
    for (int i = 0; i < 4; i++) {
        m_i[i] = -3.0e38f;
        l_i[i] = 0.f;
#pragma unroll
        for (int j = 0; j < 4; j++) acc[i][j] = 0.f;
    }

    for (int kt = 0; kt < NS / 64; kt++) {
        int sk0 = kt * 64;
        __syncthreads();    // previous iteration done with KVs/Ps
        // Load K tile transposed: KVs[d][sk]
        for (int idx = tid; idx < 1024; idx += 256) {
            int r = idx >> 4, c = (idx & 15) << 2;
            float4 v = *(const float4*)(g_k +
                ((((size_t)b * NS + sk0 + r) * NHKV + kvh) * ND + c));
            KVs[c][r] = v.x; KVs[c + 1][r] = v.y;
            KVs[c + 2][r] = v.z; KVs[c + 3][r] = v.w;
        }
        __syncthreads();

        float s[4][4];
#pragma unroll
        for (int i = 0; i < 4; i++)
#pragma unroll
            for (int j = 0; j < 4; j++) s[i][j] = 0.f;

#pragma unroll 8
        for (int dk = 0; dk < 64; dk++) {
            float a0 = Qs[ty * 4][dk];
            float a1 = Qs[ty * 4 + 1][dk];
            float a2 = Qs[ty * 4 + 2][dk];
            float a3 = Qs[ty * 4 + 3][dk];
            float4 bv = *(const float4*)&KVs[dk][tx * 4];
            s[0][0] = fmaf(a0, bv.x, s[0][0]); s[0][1] = fmaf(a0, bv.y, s[0][1]);
            s[0][2] = fmaf(a0, bv.z, s[0][2]); s[0][3] = fmaf(a0, bv.w, s[0][3]);
            s[1][0] = fmaf(a1, bv.x, s[1][0]); s[1][1] = fmaf(a1, bv.y, s[1][1]);
            s[1][2] = fmaf(a1, bv.z, s[1][2]); s[1][3] = fmaf(a1, bv.w, s[1][3]);
            s[2][0] = fmaf(a2, bv.x, s[2][0]); s[2][1] = fmaf(a2, bv.y, s[2][1]);
            s[2][2] = fmaf(a2, bv.z, s[2][2]); s[2][3] = fmaf(a2, bv.w, s[2][3]);
            s[3][0] = fmaf(a3, bv.x, s[3][0]); s[3][1] = fmaf(a3, bv.y, s[3][1]);
            s[3][2] = fmaf(a3, bv.z, s[3][2]); s[3][3] = fmaf(a3, bv.w, s[3][3]);
        }

        // additive mask [B,1,S,S]
#pragma unroll
        for (int i = 0; i < 4; i++) {
            const float* mr = mask +
                ((size_t)b * NS + sq0 + ty * 4 + i) * NS + sk0 + tx * 4;
            float4 mv = *(const float4*)mr;
            s[i][0] += mv.x; s[i][1] += mv.y; s[i][2] += mv.z; s[i][3] += mv.w;
        }

        // online softmax (rows owned by 16-lane tx groups)
#pragma unroll
        for (int i = 0; i < 4; i++) {
            float tm = fmaxf(fmaxf(s[i][0], s[i][1]), fmaxf(s[i][2], s[i][3]));
#pragma unroll
            for (int o = 8; o >= 1; o >>= 1)
                tm = fmaxf(tm, __shfl_xor_sync(0xffffffffu, tm, o));
            float m_new = fmaxf(m_i[i], tm);
            float corr = __expf(m_i[i] - m_new);
            float rs = 0.f;
#pragma unroll
            for (int j = 0; j < 4; j++) {
                float p = __expf(s[i][j] - m_new);
                Ps[ty * 4 + i][tx * 4 + j] = p;
                rs += p;
            }
#pragma unroll
            for (int o = 8; o >= 1; o >>= 1)
                rs += __shfl_xor_sync(0xffffffffu, rs, o);
            l_i[i] = l_i[i] * corr + rs;
            m_i[i] = m_new;
#pragma unroll
            for (int j = 0; j < 4; j++) acc[i][j] *= corr;
        }

        __syncthreads();    // done reading K from KVs; Ps fully written
        // Load V tile: KVs[sk][d]
        for (int idx = tid; idx < 1024; idx += 256) {
            int r = idx >> 4, c = (idx & 15) << 2;
            float4 v = *(const float4*)(g_v +
                ((((size_t)b * NS + sk0 + r) * NHKV + kvh) * ND + c));
            *(float4*)&KVs[r][c] = v;
        }
        __syncthreads();

#pragma unroll 8
        for (int kk = 0; kk < 64; kk++) {
            float p0 = Ps[ty * 4][kk];
            float p1 = Ps[ty * 4 + 1][kk];
            float p2 = Ps[ty * 4 + 2][kk];
            float p3 = Ps[ty * 4 + 3][kk];
            float4 vv = *(const float4*)&KVs[kk][tx * 4];
            acc[0][0] = fmaf(p0, vv.x, acc[0][0]); acc[0][1] = fmaf(p0, vv.y, acc[0][1]);
            acc[0][2] = fmaf(p0, vv.z, acc[0][2]); acc[0][3] = fmaf(p0, vv.w, acc[0][3]);
            acc[1][0] = fmaf(p1, vv.x, acc[1][0]); acc[1][1] = fmaf(p1, vv.y, acc[1][1]);
            acc[1][2] = fmaf(p1, vv.z, acc[1][2]); acc[1][3] = fmaf(p1, vv.w, acc[1][3]);
            acc[2][0] = fmaf(p2, vv.x, acc[2][0]); acc[2][1] = fmaf(p2, vv.y, acc[2][1]);
            acc[2][2] = fmaf(p2, vv.z, acc[2][2]); acc[2][3] = fmaf(p2, vv.w, acc[2][3]);
            acc[3][0] = fmaf(p3, vv.x, acc[3][0]); acc[3][1] = fmaf(p3, vv.y, acc[3][1]);
            acc[3][2] = fmaf(p3, vv.z, acc[3][2]); acc[3][3] = fmaf(p3, vv.w, acc[3][3]);
        }
    }

#pragma unroll
    for (int i = 0; i < 4; i++) {
        float inv = 1.f / l_i[i];
        float* dst = g_attn +
            ((((size_t)b * NS + sq0 + ty * 4 + i) * NH + h) * ND + tx * 4);
        float4 o = make_float4(acc[i][0] * inv, acc[i][1] * inv,
                               acc[i][2] * inv, acc[i][3] * inv);
        *(float4*)dst = o;
    }
}

// ---------------------------------------------------------------------------
// Launch
// ---------------------------------------------------------------------------
extern "C" void kernel_launch(void* const* d_in, const int* in_sizes, int n_in,
                              void* d_out, int out_size) {
    (void)in_sizes; (void)n_in; (void)out_size;
    const float* hs   = (const float*)d_in[0];
    const float* mask = (const float*)d_in[1];
    // d_in[2] position_ids == arange(S) for this problem (used implicitly)
    const float* cosb = (const float*)d_in[3];
    const float* sinb = (const float*)d_in[4];
    const float* Wq   = (const float*)d_in[5];
    const float* Wk   = (const float*)d_in[6];
    const float* Wv   = (const float*)d_in[7];
    const float* Wo   = (const float*)d_in[8];
    float* out = (float*)d_out;

    float *qp, *kp, *vp, *ap;
    cudaGetSymbolAddress((void**)&qp, g_q);
    cudaGetSymbolAddress((void**)&kp, g_k);
    cudaGetSymbolAddress((void**)&vp, g_v);
    cudaGetSymbolAddress((void**)&ap, g_attn);

    // Projections: M=4096, K=2048
    gemm128<<<dim3(NH * ND / 128, NB * NS / 128), 256>>>(hs, Wq, qp, NH * ND);
    gemm128<<<dim3(NHKV * ND / 128, NB * NS / 128), 256>>>(hs, Wk, kp, NHKV * ND);
    gemm128<<<dim3(NHKV * ND / 128, NB * NS / 128), 256>>>(hs, Wv, vp, NHKV * ND);

    rope_kernel<<<NB * NS, 256>>>(cosb, sinb);

    flash64<<<dim3(NS / 64, NH, NB), 256>>>(mask);

    gemm128<<<dim3(NHID / 128, NB * NS / 128), 256>>>(ap, Wo, out, NHID);
}

// round 4
// speedup vs baseline: 1.3579x; 1.3579x over previous
#include <cuda_runtime.h>
#include <cuda_bf16.h>
#include <cstdint>

// Problem constants
#define NB 2
#define NS 2048
#define NH 32
#define NHKV 8
#define ND 64
#define NHID 2048
#define NK 2048              // GEMM reduction dim (== NHID)
#define ATT_SCALE 0.125f     // 1/sqrt(64)

// ---------------------------------------------------------------------------
// Scratch (__device__ globals; no cudaMalloc allowed)
// ---------------------------------------------------------------------------
__device__ float g_q[(size_t)NB * NS * NH * ND];
__device__ float g_k[(size_t)NB * NS * NHKV * ND];
__device__ float g_v[(size_t)NB * NS * NHKV * ND];
__device__ float g_attn[(size_t)NB * NS * NH * ND];

// bf16 split buffers
__device__ __nv_bfloat16 g_ahi[(size_t)NB * NS * NK];     // activation hi
__device__ __nv_bfloat16 g_alo[(size_t)NB * NS * NK];     // activation lo
__device__ __nv_bfloat16 g_wqt_hi[(size_t)NH * ND * NK];  // Wq^T [N,K]
__device__ __nv_bfloat16 g_wqt_lo[(size_t)NH * ND * NK];
__device__ __nv_bfloat16 g_wkt_hi[(size_t)NHKV * ND * NK];
__device__ __nv_bfloat16 g_wkt_lo[(size_t)NHKV * ND * NK];
__device__ __nv_bfloat16 g_wvt_hi[(size_t)NHKV * ND * NK];
__device__ __nv_bfloat16 g_wvt_lo[(size_t)NHKV * ND * NK];
__device__ __nv_bfloat16 g_wot_hi[(size_t)NHID * NK];
__device__ __nv_bfloat16 g_wot_lo[(size_t)NHID * NK];

// ---------------------------------------------------------------------------
// Warp-MMA helpers (portable sm_80+ ISA; tcgen05 is unavailable on the
// harness's non-'a' sm_103 target)
// ---------------------------------------------------------------------------
__device__ __forceinline__ uint32_t smem_u32(const void* p) {
    uint32_t a;
    asm("{ .reg .u64 t; cvta.to.shared.u64 t, %1; cvt.u32.u64 %0, t; }"
        : "=r"(a) : "l"(p));
    return a;
}

__device__ __forceinline__ void ldsm_x4(uint32_t* r, uint32_t addr) {
    asm volatile("ldmatrix.sync.aligned.m8n8.x4.shared.b16 {%0,%1,%2,%3}, [%4];"
                 : "=r"(r[0]), "=r"(r[1]), "=r"(r[2]), "=r"(r[3]) : "r"(addr));
}

__device__ __forceinline__ void mma16816(float* c, const uint32_t* a,
                                         uint32_t b0, uint32_t b1) {
    asm volatile(
        "mma.sync.aligned.m16n8k16.row.col.f32.bf16.bf16.f32 "
        "{%0,%1,%2,%3}, {%4,%5,%6,%7}, {%8,%9}, {%0,%1,%2,%3};"
        : "+f"(c[0]), "+f"(c[1]), "+f"(c[2]), "+f"(c[3])
        : "r"(a[0]), "r"(a[1]), "r"(a[2]), "r"(a[3]), "r"(b0), "r"(b1));
}

// ---------------------------------------------------------------------------
// Prep: split fp32 -> (hi, lo) bf16, same layout
// ---------------------------------------------------------------------------
__global__ void split_f32(const float* __restrict__ X,
                          __nv_bfloat16* __restrict__ hi,
                          __nv_bfloat16* __restrict__ lo, int n4) {
    for (int i = blockIdx.x * blockDim.x + threadIdx.x; i < n4;
         i += gridDim.x * blockDim.x) {
        float4 v = ((const float4*)X)[i];
        __nv_bfloat16 h0 = __float2bfloat16(v.x);
        __nv_bfloat16 h1 = __float2bfloat16(v.y);
        __nv_bfloat16 h2 = __float2bfloat16(v.z);
        __nv_bfloat16 h3 = __float2bfloat16(v.w);
        __nv_bfloat16 l0 = __float2bfloat16(v.x - __bfloat162float(h0));
        __nv_bfloat16 l1 = __float2bfloat16(v.y - __bfloat162float(h1));
        __nv_bfloat16 l2 = __float2bfloat16(v.z - __bfloat162float(h2));
        __nv_bfloat16 l3 = __float2bfloat16(v.w - __bfloat162float(h3));
        ((__nv_bfloat162*)hi)[2 * i]     = __nv_bfloat162(h0, h1);
        ((__nv_bfloat162*)hi)[2 * i + 1] = __nv_bfloat162(h2, h3);
        ((__nv_bfloat162*)lo)[2 * i]     = __nv_bfloat162(l0, l1);
        ((__nv_bfloat162*)lo)[2 * i + 1] = __nv_bfloat162(l2, l3);
    }
}

// Prep: W[K,N] fp32 -> Wt[N,K] hi/lo bf16 (transpose + split)
__global__ void transW(const float* __restrict__ W,
                       __nv_bfloat16* __restrict__ Thi,
                       __nv_bfloat16* __restrict__ Tlo, int Ncols) {
    __shared__ float t[32][33];
    int k0 = blockIdx.x * 32, n0 = blockIdx.y * 32;
    for (int i = threadIdx.y; i < 32; i += 8)
        t[i][threadIdx.x] = W[(size_t)(k0 + i) * Ncols + n0 + threadIdx.x];
    __syncthreads();
    for (int i = threadIdx.y; i < 32; i += 8) {
        float v = t[threadIdx.x][i];  // = W[k0+tx][n0+i]
        __nv_bfloat16 h = __float2bfloat16(v);
        __nv_bfloat16 l = __float2bfloat16(v - __bfloat162float(h));
        size_t o = (size_t)(n0 + i) * NK + k0 + threadIdx.x;
        Thi[o] = h;
        Tlo[o] = l;
    }
}

// ---------------------------------------------------------------------------
// bf16x3 GEMM via mma.sync: C[M,N] = A[M,K] @ Wt[N,K]^T, fp32 accumulate.
// 128x128 CTA tile, BK=32, 256 threads (8 warps, 4x2), 32x64 warp tile.
// Smem rows padded to 40 bf16 (80B) -> conflict-free ldmatrix.
// ---------------------------------------------------------------------------
#define KPAD 40

__global__ __launch_bounds__(256) void gemm_hmma(
    const __nv_bfloat16* __restrict__ Ahi, const __nv_bfloat16* __restrict__ Alo,
    const __nv_bfloat16* __restrict__ Bhi, const __nv_bfloat16* __restrict__ Blo,
    float* __restrict__ C, int N) {
    __shared__ __nv_bfloat16 sm[4][128 * KPAD];   // Ahi, Alo, Bhi, Blo

    int tid = threadIdx.x;
    int warp = tid >> 5, lane = tid & 31;
    int wm = warp & 3, wn = warp >> 2;            // 4x2 warp grid
    int m0 = blockIdx.y * 128, n0 = blockIdx.x * 128;

    int lrow = tid >> 1;            // 0..127 (load row)
    int lc = (tid & 1) * 2;         // uint4 chunk base (0 or 2), chunks of 8 bf16

    const __nv_bfloat16* gA0 = Ahi + (size_t)(m0 + lrow) * NK;
    const __nv_bfloat16* gA1 = Alo + (size_t)(m0 + lrow) * NK;
    const __nv_bfloat16* gB0 = Bhi + (size_t)(n0 + lrow) * NK;
    const __nv_bfloat16* gB1 = Blo + (size_t)(n0 + lrow) * NK;

    float acc[2][8][4];
#pragma unroll
    for (int i = 0; i < 2; i++)
#pragma unroll
        for (int j = 0; j < 8; j++)
#pragma unroll
            for (int q = 0; q < 4; q++) acc[i][j][q] = 0.f;

    // ldmatrix source addresses (fixed per thread, varies by k16 step)
    uint32_t sA_h = smem_u32(&sm[0][(wm * 32 + (lane & 15)) * KPAD + (lane >> 4) * 8]);
    uint32_t sA_l = smem_u32(&sm[1][(wm * 32 + (lane & 15)) * KPAD + (lane >> 4) * 8]);
    uint32_t sB_h = smem_u32(&sm[2][(wn * 64 + (lane & 15)) * KPAD + (lane >> 4) * 8]);
    uint32_t sB_l = smem_u32(&sm[3][(wn * 64 + (lane & 15)) * KPAD + (lane >> 4) * 8]);

    for (int blk = 0; blk < NK / 32; blk++) {
        __syncthreads();
        int gk = blk * 32;
#pragma unroll
        for (int j = 0; j < 2; j++) {
            int c = lc + j;     // chunk 0..3 (8 bf16 each)
            uint32_t so = lrow * KPAD + c * 8;
            *(uint4*)&sm[0][so] = *(const uint4*)(gA0 + gk + c * 8);
            *(uint4*)&sm[1][so] = *(const uint4*)(gA1 + gk + c * 8);
            *(uint4*)&sm[2][so] = *(const uint4*)(gB0 + gk + c * 8);
            *(uint4*)&sm[3][so] = *(const uint4*)(gB1 + gk + c * 8);
        }
        __syncthreads();

#pragma unroll
        for (int k16 = 0; k16 < 2; k16++) {
            uint32_t koff = k16 * 16 * 2;   // byte offset along padded row
            uint32_t ah[2][4], al[2][4], bh[4][4], bl[4][4];
            ldsm_x4(ah[0], sA_h + koff);
            ldsm_x4(ah[1], sA_h + koff + 16 * KPAD * 2);
            ldsm_x4(al[0], sA_l + koff);
            ldsm_x4(al[1], sA_l + koff + 16 * KPAD * 2);
#pragma unroll
            for (int p = 0; p < 4; p++) {
                ldsm_x4(bh[p], sB_h + koff + p * 16 * KPAD * 2);
                ldsm_x4(bl[p], sB_l + koff + p * 16 * KPAD * 2);
            }
            // pass 1: hi*hi
#pragma unroll
            for (int mt = 0; mt < 2; mt++)
#pragma unroll
                for (int nt = 0; nt < 8; nt++)
                    mma16816(acc[mt][nt], ah[mt],
                             bh[nt >> 1][nt & 1], bh[nt >> 1][(nt & 1) + 2]);
            // pass 2: hi*lo
#pragma unroll
            for (int mt = 0; mt < 2; mt++)
#pragma unroll
                for (int nt = 0; nt < 8; nt++)
                    mma16816(acc[mt][nt], ah[mt],
                             bl[nt >> 1][nt & 1], bl[nt >> 1][(nt & 1) + 2]);
            // pass 3: lo*hi
#pragma unroll
            for (int mt = 0; mt < 2; mt++)
#pragma unroll
                for (int nt = 0; nt < 8; nt++)
                    mma16816(acc[mt][nt], al[mt],
                             bh[nt >> 1][nt & 1], bh[nt >> 1][(nt & 1) + 2]);
        }
    }

    // Epilogue: standard m16n8 accumulator layout
    int row = lane >> 2, col2 = (lane & 3) * 2;
#pragma unroll
    for (int mt = 0; mt < 2; mt++)
#pragma unroll
        for (int nt = 0; nt < 8; nt++) {
            float* base = C + (size_t)(m0 + wm * 32 + mt * 16 + row) * N +
                          n0 + wn * 64 + nt * 8 + col2;
            *(float2*)base = make_float2(acc[mt][nt][0], acc[mt][nt][1]);
            *(float2*)(base + 8 * (size_t)N) =
                make_float2(acc[mt][nt][2], acc[mt][nt][3]);
        }
}

// ---------------------------------------------------------------------------
// RoPE in-place on g_q and g_k (position_ids == arange(S) for this problem)
// ---------------------------------------------------------------------------
__global__ void rope_kernel(const float* __restrict__ cosb,
                            const float* __restrict__ sinb) {
    int bs = blockIdx.x;
    int s = bs & (NS - 1);
    const float* cp = cosb + (size_t)s * ND;
    const float* sp = sinb + (size_t)s * ND;
    for (int t = threadIdx.x; t < (NH + NHKV) * 32; t += blockDim.x) {
        int head = t >> 5;
        int d = t & 31;
        float* base;
        if (head < NH)
            base = g_q + (((size_t)bs * NH + head) * ND);
        else
            base = g_k + (((size_t)bs * NHKV + (head - NH)) * ND);
        float x1 = base[d];
        float x2 = base[d + 32];
        float c1 = cp[d], s1 = sp[d];
        float c2 = cp[d + 32], s2 = sp[d + 32];
        base[d]      = x1 * c1 - x2 * s1;
        base[d + 32] = x2 * c2 + x1 * s2;
    }
}

// ---------------------------------------------------------------------------
// Flash attention, fp32 scalar (unchanged this round)
// ---------------------------------------------------------------------------
__global__ __launch_bounds__(256) void flash64(const float* __restrict__ mask) {
    __shared__ float Qs[64][64];
    __shared__ float KVs[64][64];
    __shared__ float Ps[64][64];

    int tid = threadIdx.x;
    int ty = tid >> 4;
    int tx = tid & 15;
    int sq0 = blockIdx.x * 64;
    int h = blockIdx.y;
    int b = blockIdx.z;
    int kvh = h >> 2;

    for (int idx = tid; idx < 1024; idx += 256) {
        int r = idx >> 4, c = (idx & 15) << 2;
        float4 v = *(const float4*)(g_q +
            ((((size_t)b * NS + sq0 + r) * NH + h) * ND + c));
        Qs[r][c]     = v.x * ATT_SCALE;
        Qs[r][c + 1] = v.y * ATT_SCALE;
        Qs[r][c + 2] = v.z * ATT_SCALE;
        Qs[r][c + 3] = v.w * ATT_SCALE;
    }

    float m_i[4], l_i[4], acc[4][4];
#pragma unroll
    for (int i = 0; i < 4; i++) {
        m_i[i] = -3.0e38f;
        l_i[i] = 0.f;
#pragma unroll
        for (int j = 0; j < 4; j++) acc[i][j] = 0.f;
    }

    for (int kt = 0; kt < NS / 64; kt++) {
        int sk0 = kt * 64;
        __syncthreads();
        for (int idx = tid; idx < 1024; idx += 256) {
            int r = idx >> 4, c = (idx & 15) << 2;
            float4 v = *(const float4*)(g_k +
                ((((size_t)b * NS + sk0 + r) * NHKV + kvh) * ND + c));
            KVs[c][r] = v.x; KVs[c + 1][r] = v.y;
            KVs[c + 2][r] = v.z; KVs[c + 3][r] = v.w;
        }
        __syncthreads();

        float s[4][4];
#pragma unroll
        for (int i = 0; i < 4; i++)
#pragma unroll
            for (int j = 0; j < 4; j++) s[i][j] = 0.f;

#pragma unroll 8
        for (int dk = 0; dk < 64; dk++) {
            float a0 = Qs[ty * 4][dk];
            float a1 = Qs[ty * 4 + 1][dk];
            float a2 = Qs[ty * 4 + 2][dk];
            float a3 = Qs[ty * 4 + 3][dk];
            float4 bv = *(const float4*)&KVs[dk][tx * 4];
            s[0][0] = fmaf(a0, bv.x, s[0][0]); s[0][1] = fmaf(a0, bv.y, s[0][1]);
            s[0][2] = fmaf(a0, bv.z, s[0][2]); s[0][3] = fmaf(a0, bv.w, s[0][3]);
            s[1][0] = fmaf(a1, bv.x, s[1][0]); s[1][1] = fmaf(a1, bv.y, s[1][1]);
            s[1][2] = fmaf(a1, bv.z, s[1][2]); s[1][3] = fmaf(a1, bv.w, s[1][3]);
            s[2][0] = fmaf(a2, bv.x, s[2][0]); s[2][1] = fmaf(a2, bv.y, s[2][1]);
            s[2][2] = fmaf(a2, bv.z, s[2][2]); s[2][3] = fmaf(a2, bv.w, s[2][3]);
            s[3][0] = fmaf(a3, bv.x, s[3][0]); s[3][1] = fmaf(a3, bv.y, s[3][1]);
            s[3][2] = fmaf(a3, bv.z, s[3][2]); s[3][3] = fmaf(a3, bv.w, s[3][3]);
        }

#pragma unroll
        for (int i = 0; i < 4; i++) {
            const float* mr = mask +
                ((size_t)b * NS + sq0 + ty * 4 + i) * NS + sk0 + tx * 4;
            float4 mv = *(const float4*)mr;
            s[i][0] += mv.x; s[i][1] += mv.y; s[i][2] += mv.z; s[i][3] += mv.w;
        }

#pragma unroll
        for (int i = 0; i < 4; i++) {
            float tm = fmaxf(fmaxf(s[i][0], s[i][1]), fmaxf(s[i][2], s[i][3]));
#pragma unroll
            for (int o = 8; o >= 1; o >>= 1)
                tm = fmaxf(tm, __shfl_xor_sync(0xffffffffu, tm, o));
            float m_new = fmaxf(m_i[i], tm);
            float corr = __expf(m_i[i] - m_new);
            float rs = 0.f;
#pragma unroll
            for (int j = 0; j < 4; j++) {
                float p = __expf(s[i][j] - m_new);
                Ps[ty * 4 + i][tx * 4 + j] = p;
                rs += p;
            }
#pragma unroll
            for (int o = 8; o >= 1; o >>= 1)
                rs += __shfl_xor_sync(0xffffffffu, rs, o);
            l_i[i] = l_i[i] * corr + rs;
            m_i[i] = m_new;
#pragma unroll
            for (int j = 0; j < 4; j++) acc[i][j] *= corr;
        }

        __syncthreads();
        for (int idx = tid; idx < 1024; idx += 256) {
            int r = idx >> 4, c = (idx & 15) << 2;
            float4 v = *(const float4*)(g_v +
                ((((size_t)b * NS + sk0 + r) * NHKV + kvh) * ND + c));
            *(float4*)&KVs[r][c] = v;
        }
        __syncthreads();

#pragma unroll 8
        for (int kk = 0; kk < 64; kk++) {
            float p0 = Ps[ty * 4][kk];
            float p1 = Ps[ty * 4 + 1][kk];
            float p2 = Ps[ty * 4 + 2][kk];
            float p3 = Ps[ty * 4 + 3][kk];
            float4 vv = *(const float4*)&KVs[kk][tx * 4];
            acc[0][0] = fmaf(p0, vv.x, acc[0][0]); acc[0][1] = fmaf(p0, vv.y, acc[0][1]);
            acc[0][2] = fmaf(p0, vv.z, acc[0][2]); acc[0][3] = fmaf(p0, vv.w, acc[0][3]);
            acc[1][0] = fmaf(p1, vv.x, acc[1][0]); acc[1][1] = fmaf(p1, vv.y, acc[1][1]);
            acc[1][2] = fmaf(p1, vv.z, acc[1][2]); acc[1][3] = fmaf(p1, vv.w, acc[1][3]);
            acc[2][0] = fmaf(p2, vv.x, acc[2][0]); acc[2][1] = fmaf(p2, vv.y, acc[2][1]);
            acc[2][2] = fmaf(p2, vv.z, acc[2][2]); acc[2][3] = fmaf(p2, vv.w, acc[2][3]);
            acc[3][0] = fmaf(p3, vv.x, acc[3][0]); acc[3][1] = fmaf(p3, vv.y, acc[3][1]);
            acc[3][2] = fmaf(p3, vv.z, acc[3][2]); acc[3][3] = fmaf(p3, vv.w, acc[3][3]);
        }
    }

#pragma unroll
    for (int i = 0; i < 4; i++) {
        float inv = 1.f / l_i[i];
        float* dst = g_attn +
            ((((size_t)b * NS + sq0 + ty * 4 + i) * NH + h) * ND + tx * 4);
        float4 o = make_float4(acc[i][0] * inv, acc[i][1] * inv,
                               acc[i][2] * inv, acc[i][3] * inv);
        *(float4*)dst = o;
    }
}

// ---------------------------------------------------------------------------
// Launch
// ---------------------------------------------------------------------------
extern "C" void kernel_launch(void* const* d_in, const int* in_sizes, int n_in,
                              void* d_out, int out_size) {
    (void)in_sizes; (void)n_in; (void)out_size;
    const float* hs   = (const float*)d_in[0];
    const float* mask = (const float*)d_in[1];
    const float* cosb = (const float*)d_in[3];
    const float* sinb = (const float*)d_in[4];
    const float* Wq   = (const float*)d_in[5];
    const float* Wk   = (const float*)d_in[6];
    const float* Wv   = (const float*)d_in[7];
    const float* Wo   = (const float*)d_in[8];
    float* out = (float*)d_out;

    float *qp, *kp, *vp, *ap;
    cudaGetSymbolAddress((void**)&qp, g_q);
    cudaGetSymbolAddress((void**)&kp, g_k);
    cudaGetSymbolAddress((void**)&vp, g_v);
    cudaGetSymbolAddress((void**)&ap, g_attn);
    __nv_bfloat16 *ahi, *alo, *wqh, *wql, *wkh, *wkl, *wvh, *wvl, *woh, *wol;
    cudaGetSymbolAddress((void**)&ahi, g_ahi);
    cudaGetSymbolAddress((void**)&alo, g_alo);
    cudaGetSymbolAddress((void**)&wqh, g_wqt_hi);
    cudaGetSymbolAddress((void**)&wql, g_wqt_lo);
    cudaGetSymbolAddress((void**)&wkh, g_wkt_hi);
    cudaGetSymbolAddress((void**)&wkl, g_wkt_lo);
    cudaGetSymbolAddress((void**)&wvh, g_wvt_hi);
    cudaGetSymbolAddress((void**)&wvl, g_wvt_lo);
    cudaGetSymbolAddress((void**)&woh, g_wot_hi);
    cudaGetSymbolAddress((void**)&wol, g_wot_lo);

    const int M = NB * NS;           // 4096
    // --- prep: split activations + transpose/split weights ---
    split_f32<<<2048, 256>>>(hs, ahi, alo, M * NK / 4);
    transW<<<dim3(NK / 32, (NH * ND) / 32), dim3(32, 8)>>>(Wq, wqh, wql, NH * ND);
    transW<<<dim3(NK / 32, (NHKV * ND) / 32), dim3(32, 8)>>>(Wk, wkh, wkl, NHKV * ND);
    transW<<<dim3(NK / 32, (NHKV * ND) / 32), dim3(32, 8)>>>(Wv, wvh, wvl, NHKV * ND);
    transW<<<dim3(NK / 32, NHID / 32), dim3(32, 8)>>>(Wo, woh, wol, NHID);

    // --- projections (mma.sync bf16x3) ---
    gemm_hmma<<<dim3((NH * ND) / 128, M / 128), 256>>>(ahi, alo, wqh, wql, qp, NH * ND);
    gemm_hmma<<<dim3((NHKV * ND) / 128, M / 128), 256>>>(ahi, alo, wkh, wkl, kp, NHKV * ND);
    gemm_hmma<<<dim3((NHKV * ND) / 128, M / 128), 256>>>(ahi, alo, wvh, wvl, vp, NHKV * ND);

    rope_kernel<<<NB * NS, 256>>>(cosb, sinb);

    flash64<<<dim3(NS / 64, NH, NB), 256>>>(mask);

    // --- output projection ---
    split_f32<<<2048, 256>>>(ap, ahi, alo, M * NK / 4);
    gemm_hmma<<<dim3(NHID / 128, M / 128), 256>>>(ahi, alo, woh, wol, out, NHID);
}

// round 6
// speedup vs baseline: 2.5430x; 1.8727x over previous
#include <cuda_runtime.h>
#include <cuda_bf16.h>
#include <cuda_fp16.h>
#include <cstdint>

// Problem constants
#define NB 2
#define NS 2048
#define NH 32
#define NHKV 8
#define ND 64
#define NHID 2048
#define NK 2048              // GEMM reduction dim (== NHID)
#define ATT_SCALE 0.125f     // 1/sqrt(64)

// ---------------------------------------------------------------------------
// Scratch (__device__ globals; no cudaMalloc allowed)
// ---------------------------------------------------------------------------
__device__ float g_q[(size_t)NB * NS * NH * ND];
__device__ float g_k[(size_t)NB * NS * NHKV * ND];
__device__ float g_v[(size_t)NB * NS * NHKV * ND];
__device__ float g_attn[(size_t)NB * NS * NH * ND];

// bf16 split buffers (projection GEMMs)
__device__ __nv_bfloat16 g_ahi[(size_t)NB * NS * NK];
__device__ __nv_bfloat16 g_alo[(size_t)NB * NS * NK];
__device__ __nv_bfloat16 g_wqt_hi[(size_t)NH * ND * NK];
__device__ __nv_bfloat16 g_wqt_lo[(size_t)NH * ND * NK];
__device__ __nv_bfloat16 g_wkt_hi[(size_t)NHKV * ND * NK];
__device__ __nv_bfloat16 g_wkt_lo[(size_t)NHKV * ND * NK];
__device__ __nv_bfloat16 g_wvt_hi[(size_t)NHKV * ND * NK];
__device__ __nv_bfloat16 g_wvt_lo[(size_t)NHKV * ND * NK];
__device__ __nv_bfloat16 g_wot_hi[(size_t)NHID * NK];
__device__ __nv_bfloat16 g_wot_lo[(size_t)NHID * NK];

// fp16 buffers for attention (post-RoPE)
__device__ __half g_qh[(size_t)NB * NS * NH * ND];    // Q hi
__device__ __half g_ql[(size_t)NB * NS * NH * ND];    // Q lo
__device__ __half g_kh[(size_t)NB * NS * NHKV * ND];  // K (single fp16)
__device__ __half g_vh[(size_t)NB * NS * NHKV * ND];  // V hi
__device__ __half g_vl[(size_t)NB * NS * NHKV * ND];  // V lo

// ---------------------------------------------------------------------------
// Warp-MMA helpers (portable sm_80+ ISA; tcgen05 unavailable on sm_103 target)
// ---------------------------------------------------------------------------
__device__ __forceinline__ uint32_t smem_u32(const void* p) {
    uint32_t a;
    asm("{ .reg .u64 t; cvta.to.shared.u64 t, %1; cvt.u32.u64 %0, t; }"
        : "=r"(a) : "l"(p));
    return a;
}

__device__ __forceinline__ void ldsm_x4(uint32_t* r, uint32_t addr) {
    asm volatile("ldmatrix.sync.aligned.m8n8.x4.shared.b16 {%0,%1,%2,%3}, [%4];"
                 : "=r"(r[0]), "=r"(r[1]), "=r"(r[2]), "=r"(r[3]) : "r"(addr));
}
__device__ __forceinline__ void ldsm_x4_t(uint32_t* r, uint32_t addr) {
    asm volatile("ldmatrix.sync.aligned.m8n8.x4.trans.shared.b16 {%0,%1,%2,%3}, [%4];"
                 : "=r"(r[0]), "=r"(r[1]), "=r"(r[2]), "=r"(r[3]) : "r"(addr));
}

__device__ __forceinline__ void mma16816(float* c, const uint32_t* a,
                                         uint32_t b0, uint32_t b1) {
    asm volatile(
        "mma.sync.aligned.m16n8k16.row.col.f32.bf16.bf16.f32 "
        "{%0,%1,%2,%3}, {%4,%5,%6,%7}, {%8,%9}, {%0,%1,%2,%3};"
        : "+f"(c[0]), "+f"(c[1]), "+f"(c[2]), "+f"(c[3])
        : "r"(a[0]), "r"(a[1]), "r"(a[2]), "r"(a[3]), "r"(b0), "r"(b1));
}
__device__ __forceinline__ void mma16816h(float* c, const uint32_t* a,
                                          uint32_t b0, uint32_t b1) {
    asm volatile(
        "mma.sync.aligned.m16n8k16.row.col.f32.f16.f16.f32 "
        "{%0,%1,%2,%3}, {%4,%5,%6,%7}, {%8,%9}, {%0,%1,%2,%3};"
        : "+f"(c[0]), "+f"(c[1]), "+f"(c[2]), "+f"(c[3])
        : "r"(a[0]), "r"(a[1]), "r"(a[2]), "r"(a[3]), "r"(b0), "r"(b1));
}

__device__ __forceinline__ uint32_t pack_h2(float a, float b) {
    __half2 h = __floats2half2_rn(a, b);
    return *(uint32_t*)&h;
}

// ---------------------------------------------------------------------------
// Prep: split fp32 -> (hi, lo) bf16, same layout
// ---------------------------------------------------------------------------
__global__ void split_f32(const float* __restrict__ X,
                          __nv_bfloat16* __restrict__ hi,
                          __nv_bfloat16* __restrict__ lo, int n4) {
    for (int i = blockIdx.x * blockDim.x + threadIdx.x; i < n4;
         i += gridDim.x * blockDim.x) {
        float4 v = ((const float4*)X)[i];
        __nv_bfloat16 h0 = __float2bfloat16(v.x);
        __nv_bfloat16 h1 = __float2bfloat16(v.y);
        __nv_bfloat16 h2 = __float2bfloat16(v.z);
        __nv_bfloat16 h3 = __float2bfloat16(v.w);
        __nv_bfloat16 l0 = __float2bfloat16(v.x - __bfloat162float(h0));
        __nv_bfloat16 l1 = __float2bfloat16(v.y - __bfloat162float(h1));
        __nv_bfloat16 l2 = __float2bfloat16(v.z - __bfloat162float(h2));
        __nv_bfloat16 l3 = __float2bfloat16(v.w - __bfloat162float(h3));
        ((__nv_bfloat162*)hi)[2 * i]     = __nv_bfloat162(h0, h1);
        ((__nv_bfloat162*)hi)[2 * i + 1] = __nv_bfloat162(h2, h3);
        ((__nv_bfloat162*)lo)[2 * i]     = __nv_bfloat162(l0, l1);
        ((__nv_bfloat162*)lo)[2 * i + 1] = __nv_bfloat162(l2, l3);
    }
}

// Prep: W[K,N] fp32 -> Wt[N,K] hi/lo bf16 (transpose + split)
__global__ void transW(const float* __restrict__ W,
                       __nv_bfloat16* __restrict__ Thi,
                       __nv_bfloat16* __restrict__ Tlo, int Ncols) {
    __shared__ float t[32][33];
    int k0 = blockIdx.x * 32, n0 = blockIdx.y * 32;
    for (int i = threadIdx.y; i < 32; i += 8)
        t[i][threadIdx.x] = W[(size_t)(k0 + i) * Ncols + n0 + threadIdx.x];
    __syncthreads();
    for (int i = threadIdx.y; i < 32; i += 8) {
        float v = t[threadIdx.x][i];
        __nv_bfloat16 h = __float2bfloat16(v);
        __nv_bfloat16 l = __float2bfloat16(v - __bfloat162float(h));
        size_t o = (size_t)(n0 + i) * NK + k0 + threadIdx.x;
        Thi[o] = h;
        Tlo[o] = l;
    }
}

// ---------------------------------------------------------------------------
// bf16x3 GEMM via mma.sync (unchanged from R3; proven)
// ---------------------------------------------------------------------------
#define KPAD 40

__global__ __launch_bounds__(256) void gemm_hmma(
    const __nv_bfloat16* __restrict__ Ahi, const __nv_bfloat16* __restrict__ Alo,
    const __nv_bfloat16* __restrict__ Bhi, const __nv_bfloat16* __restrict__ Blo,
    float* __restrict__ C, int N) {
    __shared__ __nv_bfloat16 sm[4][128 * KPAD];

    int tid = threadIdx.x;
    int warp = tid >> 5, lane = tid & 31;
    int wm = warp & 3, wn = warp >> 2;
    int m0 = blockIdx.y * 128, n0 = blockIdx.x * 128;

    int lrow = tid >> 1;
    int lc = (tid & 1) * 2;

    const __nv_bfloat16* gA0 = Ahi + (size_t)(m0 + lrow) * NK;
    const __nv_bfloat16* gA1 = Alo + (size_t)(m0 + lrow) * NK;
    const __nv_bfloat16* gB0 = Bhi + (size_t)(n0 + lrow) * NK;
    const __nv_bfloat16* gB1 = Blo + (size_t)(n0 + lrow) * NK;

    float acc[2][8][4];
#pragma unroll
    for (int i = 0; i < 2; i++)
#pragma unroll
        for (int j = 0; j < 8; j++)
#pragma unroll
            for (int q = 0; q < 4; q++) acc[i][j][q] = 0.f;

    uint32_t sA_h = smem_u32(&sm[0][(wm * 32 + (lane & 15)) * KPAD + (lane >> 4) * 8]);
    uint32_t sA_l = smem_u32(&sm[1][(wm * 32 + (lane & 15)) * KPAD + (lane >> 4) * 8]);
    uint32_t sB_h = smem_u32(&sm[2][(wn * 64 + (lane & 15)) * KPAD + (lane >> 4) * 8]);
    uint32_t sB_l = smem_u32(&sm[3][(wn * 64 + (lane & 15)) * KPAD + (lane >> 4) * 8]);

    for (int blk = 0; blk < NK / 32; blk++) {
        __syncthreads();
        int gk = blk * 32;
#pragma unroll
        for (int j = 0; j < 2; j++) {
            int c = lc + j;
            uint32_t so = lrow * KPAD + c * 8;
            *(uint4*)&sm[0][so] = *(const uint4*)(gA0 + gk + c * 8);
            *(uint4*)&sm[1][so] = *(const uint4*)(gA1 + gk + c * 8);
            *(uint4*)&sm[2][so] = *(const uint4*)(gB0 + gk + c * 8);
            *(uint4*)&sm[3][so] = *(const uint4*)(gB1 + gk + c * 8);
        }
        __syncthreads();

#pragma unroll
        for (int k16 = 0; k16 < 2; k16++) {
            uint32_t koff = k16 * 16 * 2;
            uint32_t ah[2][4], al[2][4], bh[4][4], bl[4][4];
            ldsm_x4(ah[0], sA_h + koff);
            ldsm_x4(ah[1], sA_h + koff + 16 * KPAD * 2);
            ldsm_x4(al[0], sA_l + koff);
            ldsm_x4(al[1], sA_l + koff + 16 * KPAD * 2);
#pragma unroll
            for (int p = 0; p < 4; p++) {
                ldsm_x4(bh[p], sB_h + koff + p * 16 * KPAD * 2);
                ldsm_x4(bl[p], sB_l + koff + p * 16 * KPAD * 2);
            }
#pragma unroll
            for (int mt = 0; mt < 2; mt++)
#pragma unroll
                for (int nt = 0; nt < 8; nt++)
                    mma16816(acc[mt][nt], ah[mt],
                             bh[nt >> 1][nt & 1], bh[nt >> 1][(nt & 1) + 2]);
#pragma unroll
            for (int mt = 0; mt < 2; mt++)
#pragma unroll
                for (int nt = 0; nt < 8; nt++)
                    mma16816(acc[mt][nt], ah[mt],
                             bl[nt >> 1][nt & 1], bl[nt >> 1][(nt & 1) + 2]);
#pragma unroll
            for (int mt = 0; mt < 2; mt++)
#pragma unroll
                for (int nt = 0; nt < 8; nt++)
                    mma16816(acc[mt][nt], al[mt],
                             bh[nt >> 1][nt & 1], bh[nt >> 1][(nt & 1) + 2]);
        }
    }

    int row = lane >> 2, col2 = (lane & 3) * 2;
#pragma unroll
    for (int mt = 0; mt < 2; mt++)
#pragma unroll
        for (int nt = 0; nt < 8; nt++) {
            float* base = C + (size_t)(m0 + wm * 32 + mt * 16 + row) * N +
                          n0 + wn * 64 + nt * 8 + col2;
            *(float2*)base = make_float2(acc[mt][nt][0], acc[mt][nt][1]);
            *(float2*)(base + 8 * (size_t)N) =
                make_float2(acc[mt][nt][2], acc[mt][nt][3]);
        }
}

// ---------------------------------------------------------------------------
// RoPE + fp16 conversion: g_q -> (g_qh, g_ql), g_k -> g_kh.
// position_ids == arange(S) for this problem.
// ---------------------------------------------------------------------------
__global__ void rope_split(const float* __restrict__ cosb,
                           const float* __restrict__ sinb) {
    int bs = blockIdx.x;
    int s = bs & (NS - 1);
    const float* cp = cosb + (size_t)s * ND;
    const float* sp = sinb + (size_t)s * ND;
    for (int t = threadIdx.x; t < (NH + NHKV) * 32; t += blockDim.x) {
        int head = t >> 5;
        int d = t & 31;
        float c1 = cp[d], s1 = sp[d];
        float c2 = cp[d + 32], s2 = sp[d + 32];
        if (head < NH) {
            size_t off = ((size_t)bs * NH + head) * ND;
            float x1 = g_q[off + d], x2 = g_q[off + d + 32];
            float y1 = x1 * c1 - x2 * s1;
            float y2 = x2 * c2 + x1 * s2;
            __half h1 = __float2half(y1);
            __half h2 = __float2half(y2);
            g_qh[off + d] = h1;
            g_qh[off + d + 32] = h2;
            g_ql[off + d] = __float2half(y1 - __half2float(h1));
            g_ql[off + d + 32] = __float2half(y2 - __half2float(h2));
        } else {
            size_t off = ((size_t)bs * NHKV + (head - NH)) * ND;
            float x1 = g_k[off + d], x2 = g_k[off + d + 32];
            g_kh[off + d] = __float2half(x1 * c1 - x2 * s1);
            g_kh[off + d + 32] = __float2half(x2 * c2 + x1 * s2);
        }
    }
}

// V fp32 -> fp16 hi/lo
__global__ void conv_v(int n4) {
    for (int i = blockIdx.x * blockDim.x + threadIdx.x; i < n4;
         i += gridDim.x * blockDim.x) {
        float4 v = ((const float4*)g_v)[i];
        __half h0 = __float2half(v.x), h1 = __float2half(v.y);
        __half h2 = __float2half(v.z), h3 = __float2half(v.w);
        ((uint32_t*)g_vh)[2 * i]     = pack_h2(v.x, v.y);
        ((uint32_t*)g_vh)[2 * i + 1] = pack_h2(v.z, v.w);
        ((uint32_t*)g_vl)[2 * i] =
            pack_h2(v.x - __half2float(h0), v.y - __half2float(h1));
        ((uint32_t*)g_vl)[2 * i + 1] =
            pack_h2(v.z - __half2float(h2), v.w - __half2float(h3));
    }
}

// ---------------------------------------------------------------------------
// HMMA flash attention. grid = (NS/128, NH, NB), 256 threads (8 warps).
// Warp owns 16 q rows. BN=64 keys per block. fp16 split precision:
//   QK: (qh + ql) x kh  (2 passes)   PV: p x (vh + vl)  (2 passes)
// ---------------------------------------------------------------------------
#define FPAD 72   // halves per smem row (64 + 8 pad) -> conflict-free ldmatrix

__global__ __launch_bounds__(256) void flash_hmma(const float* __restrict__ mask) {
    __shared__ __half sK[64 * FPAD];
    __shared__ __half sVh[64 * FPAD];
    __shared__ __half sVl[64 * FPAD];

    const int tid = threadIdx.x;
    const int warp = tid >> 5, lane = tid & 31;
    const int b = blockIdx.z, h = blockIdx.y;
    const int sq0 = blockIdx.x * 128;
    const int kvh = h >> 2;
    const int r = lane >> 2, c2 = (lane & 3) * 2;
    const int qrow = sq0 + warp * 16 + r;

    // Q fragments hi/lo (registers, loaded once)
    uint32_t qh[4][4], ql[4][4];
#pragma unroll
    for (int ks = 0; ks < 4; ks++)
#pragma unroll
        for (int idx = 0; idx < 4; idx++) {
            int row = qrow + (idx & 1) * 8;
            int d = ks * 16 + c2 + (idx >> 1) * 8;
            size_t off = (((size_t)b * NS + row) * NH + h) * ND + d;
            qh[ks][idx] = *(const uint32_t*)((const char*)g_qh + off * 2);
            ql[ks][idx] = *(const uint32_t*)((const char*)g_ql + off * 2);
        }

    float o_acc[8][4];
#pragma unroll
    for (int t = 0; t < 8; t++)
#pragma unroll
        for (int j = 0; j < 4; j++) o_acc[t][j] = 0.f;
    float m_i[2] = {-3.0e38f, -3.0e38f};
    float l_i[2] = {0.f, 0.f};

    // smem load indexing: idx = tid*2+j -> row=idx>>3, ch=idx&7 (8 uint4 per row)
    for (int kt = 0; kt < 32; kt++) {
        int sk0 = kt * 64;
        __syncthreads();
#pragma unroll
        for (int j = 0; j < 2; j++) {
            int idx = tid * 2 + j;
            int row = idx >> 3, ch = idx & 7;
            size_t goff = (((size_t)b * NS + sk0 + row) * NHKV + kvh) * ND + ch * 8;
            int soff = row * FPAD + ch * 8;
            *(uint4*)(sK + soff)  = *(const uint4*)(g_kh + goff);
            *(uint4*)(sVh + soff) = *(const uint4*)(g_vh + goff);
            *(uint4*)(sVl + soff) = *(const uint4*)(g_vl + goff);
        }
        __syncthreads();

        // --- QK^T ---
        float s_acc[8][4];
#pragma unroll
        for (int t = 0; t < 8; t++)
#pragma unroll
            for (int j = 0; j < 4; j++) s_acc[t][j] = 0.f;

#pragma unroll
        for (int ks = 0; ks < 4; ks++) {
#pragma unroll
            for (int tp = 0; tp < 4; tp++) {
                uint32_t kb[4];
                ldsm_x4(kb, smem_u32(sK + (tp * 16 + (lane & 15)) * FPAD +
                                     ks * 16 + (lane >> 4) * 8));
                mma16816h(s_acc[2 * tp],     qh[ks], kb[0], kb[2]);
                mma16816h(s_acc[2 * tp],     ql[ks], kb[0], kb[2]);
                mma16816h(s_acc[2 * tp + 1], qh[ks], kb[1], kb[3]);
                mma16816h(s_acc[2 * tp + 1], ql[ks], kb[1], kb[3]);
            }
        }

        // --- mask + scale + online softmax ---
        float corr[2];
#pragma unroll
        for (int i = 0; i < 2; i++) {
            int grow = qrow + i * 8;
            const float* mrow = mask + ((size_t)b * NS + grow) * NS + sk0;
            float mx = -3.0e38f;
#pragma unroll
            for (int t = 0; t < 8; t++) {
                float2 mv = *(const float2*)(mrow + t * 8 + c2);
                s_acc[t][2 * i]     = fmaf(s_acc[t][2 * i],     ATT_SCALE, mv.x);
                s_acc[t][2 * i + 1] = fmaf(s_acc[t][2 * i + 1], ATT_SCALE, mv.y);
                mx = fmaxf(mx, fmaxf(s_acc[t][2 * i], s_acc[t][2 * i + 1]));
            }
            mx = fmaxf(mx, __shfl_xor_sync(0xffffffffu, mx, 1));
            mx = fmaxf(mx, __shfl_xor_sync(0xffffffffu, mx, 2));
            float mnew = fmaxf(m_i[i], mx);
            corr[i] = __expf(m_i[i] - mnew);
            float rs = 0.f;
#pragma unroll
            for (int t = 0; t < 8; t++) {
                float p0 = __expf(s_acc[t][2 * i] - mnew);
                float p1 = __expf(s_acc[t][2 * i + 1] - mnew);
                s_acc[t][2 * i] = p0;
                s_acc[t][2 * i + 1] = p1;
                rs += p0 + p1;
            }
            rs += __shfl_xor_sync(0xffffffffu, rs, 1);
            rs += __shfl_xor_sync(0xffffffffu, rs, 2);
            l_i[i] = l_i[i] * corr[i] + rs;
            m_i[i] = mnew;
        }

        // rescale O accumulators
#pragma unroll
        for (int t = 0; t < 8; t++) {
            o_acc[t][0] *= corr[0]; o_acc[t][1] *= corr[0];
            o_acc[t][2] *= corr[1]; o_acc[t][3] *= corr[1];
        }

        // P -> fp16 A fragments (in registers)
        uint32_t pa[4][4];
#pragma unroll
        for (int kj = 0; kj < 4; kj++) {
            pa[kj][0] = pack_h2(s_acc[2 * kj][0],     s_acc[2 * kj][1]);
            pa[kj][1] = pack_h2(s_acc[2 * kj][2],     s_acc[2 * kj][3]);
            pa[kj][2] = pack_h2(s_acc[2 * kj + 1][0], s_acc[2 * kj + 1][1]);
            pa[kj][3] = pack_h2(s_acc[2 * kj + 1][2], s_acc[2 * kj + 1][3]);
        }

        // --- P·V ---
#pragma unroll
        for (int kj = 0; kj < 4; kj++) {
#pragma unroll
            for (int dp = 0; dp < 4; dp++) {
                uint32_t vb[4];
                uint32_t soff = (kj * 16 + (lane & 15)) * FPAD +
                                dp * 16 + (lane >> 4) * 8;
                ldsm_x4_t(vb, smem_u32(sVh + soff));
                mma16816h(o_acc[2 * dp],     pa[kj], vb[0], vb[1]);
                mma16816h(o_acc[2 * dp + 1], pa[kj], vb[2], vb[3]);
                ldsm_x4_t(vb, smem_u32(sVl + soff));
                mma16816h(o_acc[2 * dp],     pa[kj], vb[0], vb[1]);
                mma16816h(o_acc[2 * dp + 1], pa[kj], vb[2], vb[3]);
            }
        }
    }

    // epilogue
    float inv0 = 1.f / l_i[0], inv1 = 1.f / l_i[1];
#pragma unroll
    for (int t = 0; t < 8; t++) {
        size_t b0 = (((size_t)b * NS + qrow) * NH + h) * ND + t * 8 + c2;
        *(float2*)(g_attn + b0) =
            make_float2(o_acc[t][0] * inv0, o_acc[t][1] * inv0);
        size_t b1 = (((size_t)b * NS + qrow + 8) * NH + h) * ND + t * 8 + c2;
        *(float2*)(g_attn + b1) =
            make_float2(o_acc[t][2] * inv1, o_acc[t][3] * inv1);
    }
}

// ---------------------------------------------------------------------------
// Launch
// ---------------------------------------------------------------------------
extern "C" void kernel_launch(void* const* d_in, const int* in_sizes, int n_in,
                              void* d_out, int out_size) {
    (void)in_sizes; (void)n_in; (void)out_size;
    const float* hs   = (const float*)d_in[0];
    const float* mask = (const float*)d_in[1];
    const float* cosb = (const float*)d_in[3];
    const float* sinb = (const float*)d_in[4];
    const float* Wq   = (const float*)d_in[5];
    const float* Wk   = (const float*)d_in[6];
    const float* Wv   = (const float*)d_in[7];
    const float* Wo   = (const float*)d_in[8];
    float* out = (float*)d_out;

    float *qp, *kp, *vp, *ap;
    cudaGetSymbolAddress((void**)&qp, g_q);
    cudaGetSymbolAddress((void**)&kp, g_k);
    cudaGetSymbolAddress((void**)&vp, g_v);
    cudaGetSymbolAddress((void**)&ap, g_attn);
    __nv_bfloat16 *ahi, *alo, *wqh, *wql, *wkh, *wkl, *wvh, *wvl, *woh, *wol;
    cudaGetSymbolAddress((void**)&ahi, g_ahi);
    cudaGetSymbolAddress((void**)&alo, g_alo);
    cudaGetSymbolAddress((void**)&wqh, g_wqt_hi);
    cudaGetSymbolAddress((void**)&wql, g_wqt_lo);
    cudaGetSymbolAddress((void**)&wkh, g_wkt_hi);
    cudaGetSymbolAddress((void**)&wkl, g_wkt_lo);
    cudaGetSymbolAddress((void**)&wvh, g_wvt_hi);
    cudaGetSymbolAddress((void**)&wvl, g_wvt_lo);
    cudaGetSymbolAddress((void**)&woh, g_wot_hi);
    cudaGetSymbolAddress((void**)&wol, g_wot_lo);

    const int M = NB * NS;           // 4096
    // --- prep: split activations + transpose/split weights ---
    split_f32<<<2048, 256>>>(hs, ahi, alo, M * NK / 4);
    transW<<<dim3(NK / 32, (NH * ND) / 32), dim3(32, 8)>>>(Wq, wqh, wql, NH * ND);
    transW<<<dim3(NK / 32, (NHKV * ND) / 32), dim3(32, 8)>>>(Wk, wkh, wkl, NHKV * ND);
    transW<<<dim3(NK / 32, (NHKV * ND) / 32), dim3(32, 8)>>>(Wv, wvh, wvl, NHKV * ND);
    transW<<<dim3(NK / 32, NHID / 32), dim3(32, 8)>>>(Wo, woh, wol, NHID);

    // --- projections (mma.sync bf16x3) ---
    gemm_hmma<<<dim3((NH * ND) / 128, M / 128), 256>>>(ahi, alo, wqh, wql, qp, NH * ND);
    gemm_hmma<<<dim3((NHKV * ND) / 128, M / 128), 256>>>(ahi, alo, wkh, wkl, kp, NHKV * ND);
    gemm_hmma<<<dim3((NHKV * ND) / 128, M / 128), 256>>>(ahi, alo, wvh, wvl, vp, NHKV * ND);

    // --- RoPE + fp16 conversion ---
    rope_split<<<NB * NS, 256>>>(cosb, sinb);
    conv_v<<<1024, 256>>>(NB * NS * NHKV * ND / 4);

    // --- HMMA flash attention ---
    flash_hmma<<<dim3(NS / 128, NH, NB), 256>>>(mask);

    // --- output projection ---
    split_f32<<<2048, 256>>>(ap, ahi, alo, M * NK / 4);
    gemm_hmma<<<dim3(NHID / 128, M / 128), 256>>>(ahi, alo, woh, wol, out, NHID);
}